// round 2
// baseline (speedup 1.0000x reference)
#include <cuda_runtime.h>

// Word2Vec negative-sampling loss:
//   out[b,0]   = softplus(-dot(syn0[inputs[b]], syn1[labels[b]]))
//   out[b,1+n] = softplus( dot(syn0[inputs[b]], syn1[sampled[n,b]]))
// B=16384, H=128, N=5, V=1e6.
//
// R2: 2 batch elements per warp. All 14 index loads then all 14 row loads
// (LDG.128, 512B/row/warp) are front-batched for max MLP; grid = 1024 blocks
// -> one full wave on 148 SMs (no wave-2 tail).

#define H 128
#define NNEG 5
#define NT (1 + NNEG)      // rows of syn1 per element
#define EPW 2              // elements per warp

__global__ __launch_bounds__(256) void w2v_kernel(
    const int* __restrict__ inputs,
    const int* __restrict__ labels,
    const int* __restrict__ sampled,   // [N, B]
    const float* __restrict__ syn0,    // [V, H]
    const float* __restrict__ syn1,    // [V, H]
    float* __restrict__ out,           // [B, 1+N]
    int B)
{
    const int warp = (blockIdx.x * blockDim.x + threadIdx.x) >> 5;
    const int lane = threadIdx.x & 31;
    const int nwarps = (gridDim.x * blockDim.x) >> 5;

    int b[EPW];
#pragma unroll
    for (int e = 0; e < EPW; e++) b[e] = warp + e * nwarps;
    if (b[0] >= B) return;

    // ---- Phase 1: all index loads (broadcast within warp) ----
    int inp[EPW];
    int tgt[EPW][NT];
#pragma unroll
    for (int e = 0; e < EPW; e++) {
        inp[e]    = __ldg(&inputs[b[e]]);
        tgt[e][0] = __ldg(&labels[b[e]]);
#pragma unroll
        for (int n = 0; n < NNEG; n++)
            tgt[e][1 + n] = __ldg(&sampled[n * B + b[e]]);
    }

    // ---- Phase 2: all row loads front-batched (14 x LDG.128 per lane) ----
    const int hoff = lane * 4;
    float4 u[EPW];
#pragma unroll
    for (int e = 0; e < EPW; e++)
        u[e] = *reinterpret_cast<const float4*>(
            syn0 + (long long)inp[e] * H + hoff);

    float4 v[EPW][NT];
#pragma unroll
    for (int e = 0; e < EPW; e++)
#pragma unroll
        for (int t = 0; t < NT; t++)
            v[e][t] = *reinterpret_cast<const float4*>(
                syn1 + (long long)tgt[e][t] * H + hoff);

    // ---- Phase 3: dots + butterfly reductions ----
    float dot[EPW][NT];
#pragma unroll
    for (int e = 0; e < EPW; e++)
#pragma unroll
        for (int t = 0; t < NT; t++) {
            float d = u[e].x * v[e][t].x + u[e].y * v[e][t].y
                    + u[e].z * v[e][t].z + u[e].w * v[e][t].w;
#pragma unroll
            for (int o = 16; o > 0; o >>= 1)
                d += __shfl_xor_sync(0xffffffffu, d, o);
            dot[e][t] = d;
        }

    // ---- Phase 4: softplus + store (lane 0) ----
    if (lane == 0) {
#pragma unroll
        for (int e = 0; e < EPW; e++) {
            float x0 = -dot[e][0];
            out[b[e] * NT + 0] = fmaxf(x0, 0.0f) + log1pf(__expf(-fabsf(x0)));
#pragma unroll
            for (int t = 1; t < NT; t++) {
                float x = dot[e][t];
                out[b[e] * NT + t] = fmaxf(x, 0.0f) + log1pf(__expf(-fabsf(x)));
            }
        }
    }
}

extern "C" void kernel_launch(void* const* d_in, const int* in_sizes, int n_in,
                              void* d_out, int out_size)
{
    const int*   inputs  = (const int*)d_in[0];
    const int*   labels  = (const int*)d_in[1];
    const int*   sampled = (const int*)d_in[2];
    const float* syn0    = (const float*)d_in[3];
    const float* syn1    = (const float*)d_in[4];
    float*       out     = (float*)d_out;

    const int B = in_sizes[0];
    const int threads = 256;                        // 8 warps/block
    const int warps_needed = (B + EPW - 1) / EPW;   // 8192
    const int blocks = (warps_needed * 32 + threads - 1) / threads;  // 1024
    w2v_kernel<<<blocks, threads>>>(inputs, labels, sampled, syn0, syn1, out, B);
}

// round 3
// speedup vs baseline: 1.1604x; 1.1604x over previous
#include <cuda_runtime.h>
#include <cstdint>

// Word2Vec negative-sampling loss, R3: cp.async double-buffered gather pipeline.
//   out[b,0]   = softplus(-dot(syn0[inputs[b]], syn1[labels[b]]))
//   out[b,1+n] = softplus( dot(syn0[inputs[b]], syn1[sampled[n,b]]))
// B=16384, H=128 (row = 512B), N=5 -> 7 gathered rows per element.
//
// One warp per element-stream; each warp processes ~4 elements. Rows for
// element k+1 stream into smem via cp.async while element k is computed from
// smem -> loads are in flight ~100% of warp lifetime (vs ~40% register-resident).

#define H 128
#define NROW 7            // 1 syn0 row + 6 syn1 rows
#define WPB 4             // warps per block (128 threads)

__device__ __forceinline__ void cpa16(uint32_t dst_smem, const void* src) {
    asm volatile("cp.async.cg.shared.global [%0], [%1], 16;"
                 :: "r"(dst_smem), "l"(src) : "memory");
}
__device__ __forceinline__ void cpa_commit() {
    asm volatile("cp.async.commit_group;" ::: "memory");
}
template <int N>
__device__ __forceinline__ void cpa_wait() {
    asm volatile("cp.async.wait_group %0;" :: "n"(N) : "memory");
}

__global__ __launch_bounds__(32 * WPB) void w2v_kernel(
    const int* __restrict__ inputs,
    const int* __restrict__ labels,
    const int* __restrict__ sampled,   // [N, B]
    const float* __restrict__ syn0,    // [V, H]
    const float* __restrict__ syn1,    // [V, H]
    float* __restrict__ out,           // [B, 6]
    int B)
{
    __shared__ float4 buf[WPB][2][NROW][32];   // 28,672 B

    const int w    = threadIdx.x >> 5;
    const int lane = threadIdx.x & 31;
    const int gwarp = blockIdx.x * WPB + w;
    const int W = gridDim.x * WPB;             // total warps

    if (gwarp >= B) return;
    const int hoff = lane * 4;

    // ---- helpers ----
    auto ldidx = [&](int b, int* t) {
        t[0] = __ldg(inputs + b);              // syn0 row index
        t[1] = __ldg(labels + b);
#pragma unroll
        for (int n = 0; n < 5; n++) t[2 + n] = __ldg(sampled + n * B + b);
    };
    auto issue = [&](int stage, const int* t) {
        uint32_t d0 = (uint32_t)__cvta_generic_to_shared(&buf[w][stage][0][lane]);
        cpa16(d0, syn0 + ((size_t)(unsigned)t[0] << 7) + hoff);
#pragma unroll
        for (int r = 1; r < NROW; r++) {
            uint32_t d = (uint32_t)__cvta_generic_to_shared(&buf[w][stage][r][lane]);
            cpa16(d, syn1 + ((size_t)(unsigned)t[r] << 7) + hoff);
        }
        cpa_commit();
    };

    // ---- prologue: fill both stages ----
    int idx[NROW];
    ldidx(gwarp, idx);
    issue(0, idx);

    const int b1 = gwarp + W;
    if (b1 < B) { ldidx(b1, idx); issue(1, idx); }

    // ---- steady loop ----
    int bn = gwarp + 2 * W;                    // element to prefetch (k+2)
    int k = 0;
    for (int bk = gwarp; bk < B; bk += W, k++) {
        int idxn[NROW];
        const bool hasn = (bn < B);
        if (hasn) ldidx(bn, idxn);             // index prefetch overlaps the wait

        if (bk + W < B) cpa_wait<1>();         // e_k done, e_{k+1} still in flight
        else            cpa_wait<0>();

        const int st = k & 1;
        float4 u = buf[w][st][0][lane];
        float dot[6];
#pragma unroll
        for (int t = 0; t < 6; t++) {
            float4 v = buf[w][st][1 + t][lane];
            float d = u.x * v.x + u.y * v.y + u.z * v.z + u.w * v.w;
#pragma unroll
            for (int o = 16; o > 0; o >>= 1)
                d += __shfl_xor_sync(0xffffffffu, d, o);
            dot[t] = d;
        }

        if (lane == 0) {
            float x0 = -dot[0];
            out[bk * 6 + 0] = fmaxf(x0, 0.0f) + log1pf(__expf(-fabsf(x0)));
#pragma unroll
            for (int t = 1; t < 6; t++) {
                float x = dot[t];
                out[bk * 6 + t] = fmaxf(x, 0.0f) + log1pf(__expf(-fabsf(x)));
            }
        }

        if (hasn) issue(st, idxn);             // refill the stage just drained
        bn += W;
    }
}

extern "C" void kernel_launch(void* const* d_in, const int* in_sizes, int n_in,
                              void* d_out, int out_size)
{
    const int*   inputs  = (const int*)d_in[0];
    const int*   labels  = (const int*)d_in[1];
    const int*   sampled = (const int*)d_in[2];
    const float* syn0    = (const float*)d_in[3];
    const float* syn1    = (const float*)d_in[4];
    float*       out     = (float*)d_out;

    const int B = in_sizes[0];
    // ~4 elements per warp; B=16384 -> 4096 warps -> 1024 blocks (one full wave)
    int warps  = (B + 3) / 4;
    int blocks = (warps + WPB - 1) / WPB;
    w2v_kernel<<<blocks, 32 * WPB>>>(inputs, labels, sampled, syn0, syn1, out, B);
}

// round 4
// speedup vs baseline: 1.1995x; 1.0337x over previous
#include <cuda_runtime.h>
#include <cstdint>

// Word2Vec negative-sampling loss, R4:
//   out[b,0]   = softplus(-dot(syn0[inputs[b]], syn1[labels[b]]))
//   out[b,1+n] = softplus( dot(syn0[inputs[b]], syn1[sampled[n,b]]))
// B=16384, H=128 (512B rows), N=5 -> 7 gathered rows/element.
//
// 16-lane groups: one warp = 2 elements per pipeline stage. cp.async
// double-buffered smem pipeline; reductions are 4-shfl (within 16-lane
// halves) and cover both elements per instruction.

#define H 128
#define NROW 7
#define WPB 3              // warps per block (96 threads); 42KB static smem

__device__ __forceinline__ void cpa16(uint32_t dst_smem, const void* src) {
    asm volatile("cp.async.cg.shared.global [%0], [%1], 16;"
                 :: "r"(dst_smem), "l"(src) : "memory");
}
__device__ __forceinline__ void cpa_commit() {
    asm volatile("cp.async.commit_group;" ::: "memory");
}
template <int N>
__device__ __forceinline__ void cpa_wait() {
    asm volatile("cp.async.wait_group %0;" :: "n"(N) : "memory");
}

__global__ __launch_bounds__(32 * WPB) void w2v_kernel(
    const int* __restrict__ inputs,
    const int* __restrict__ labels,
    const int* __restrict__ sampled,   // [N, B]
    const float* __restrict__ syn0,    // [V, H]
    const float* __restrict__ syn1,    // [V, H]
    float* __restrict__ out,           // [B, 6]
    int B)
{
    // [warp][stage][row][chunk][lane] : lane l holds element (l>>4),
    // row floats [(l&15)*4 + chunk*64 .. +4)
    __shared__ float4 buf[WPB][2][NROW][2][32];   // 43,008 B

    const int w     = threadIdx.x >> 5;
    const int lane  = threadIdx.x & 31;
    const int half  = lane >> 4;           // which element of the pair
    const int sub   = lane & 15;           // lane within 16-group
    const int gwarp = blockIdx.x * WPB + w;
    const int W     = gridDim.x * WPB;     // total warps
    const int NP    = (B + 1) >> 1;        // total pairs

    if (gwarp >= NP) return;

    // per-lane element index for pair p:  b = 2p + half  (clamped for loads)
    auto ldidx = [&](int p, int* t) {
        int b = 2 * p + half;
        if (b >= B) b = B - 1;             // clamp: safe dup loads
        t[0] = __ldg(inputs + b);
        t[1] = __ldg(labels + b);
#pragma unroll
        for (int n = 0; n < 5; n++) t[2 + n] = __ldg(sampled + n * B + b);
    };

    auto issue = [&](int st, const int* t) {
#pragma unroll
        for (int r = 0; r < NROW; r++) {
            const float* base = (r == 0 ? syn0 : syn1)
                              + ((size_t)(unsigned)t[r] << 7) + sub * 4;
#pragma unroll
            for (int c = 0; c < 2; c++) {
                uint32_t d = (uint32_t)__cvta_generic_to_shared(
                    &buf[w][st][r][c][lane]);
                cpa16(d, base + c * 64);
            }
        }
        cpa_commit();
    };

    // ---- prologue: fill both stages ----
    int idx[NROW];
    ldidx(gwarp, idx);
    issue(0, idx);
    if (gwarp + W < NP) { ldidx(gwarp + W, idx); issue(1, idx); }

    // ---- steady loop over pairs ----
    int pn = gwarp + 2 * W;                // pair to prefetch (k+2)
    int k = 0;
    for (int p = gwarp; p < NP; p += W, k++) {
        int idxn[NROW];
        const bool hasn = (pn < NP);
        if (hasn) ldidx(pn, idxn);         // index prefetch overlaps the wait

        if (p + W < NP) cpa_wait<1>();
        else            cpa_wait<0>();

        const int st = k & 1;
        const float4 u0 = buf[w][st][0][0][lane];
        const float4 u1 = buf[w][st][0][1][lane];

        float dot[6];
#pragma unroll
        for (int t = 0; t < 6; t++) {
            float4 v0 = buf[w][st][1 + t][0][lane];
            float4 v1 = buf[w][st][1 + t][1][lane];
            float d = u0.x * v0.x + u0.y * v0.y + u0.z * v0.z + u0.w * v0.w
                    + u1.x * v1.x + u1.y * v1.y + u1.z * v1.z + u1.w * v1.w;
#pragma unroll
            for (int o = 8; o > 0; o >>= 1)          // reduce within 16 lanes
                d += __shfl_xor_sync(0xffffffffu, d, o);
            dot[t] = d;
        }

        if (sub == 0) {                    // lanes 0 and 16: one element each
            int b = 2 * p + half;
            if (b < B) {
                float x0 = -dot[0];
                out[b * 6 + 0] = fmaxf(x0, 0.0f) + log1pf(__expf(-fabsf(x0)));
#pragma unroll
                for (int t = 1; t < 6; t++) {
                    float x = dot[t];
                    out[b * 6 + t] = fmaxf(x, 0.0f) + log1pf(__expf(-fabsf(x)));
                }
            }
        }

        if (hasn) issue(st, idxn);         // refill the drained stage
        pn += W;
    }
}

extern "C" void kernel_launch(void* const* d_in, const int* in_sizes, int n_in,
                              void* d_out, int out_size)
{
    const int*   inputs  = (const int*)d_in[0];
    const int*   labels  = (const int*)d_in[1];
    const int*   sampled = (const int*)d_in[2];
    const float* syn0    = (const float*)d_in[3];
    const float* syn1    = (const float*)d_in[4];
    float*       out     = (float*)d_out;

    const int B  = in_sizes[0];
    const int NP = (B + 1) / 2;                    // pairs
    int warps  = (NP + 3) / 4;                     // ~4 pairs (8 elems) per warp
    int blocks = (warps + WPB - 1) / WPB;          // ~683 -> single wave
    w2v_kernel<<<blocks, 32 * WPB>>>(inputs, labels, sampled, syn0, syn1, out, B);
}